// round 1
// baseline (speedup 1.0000x reference)
#include <cuda_runtime.h>
#include <math.h>

#define T 20
#define NC 80
#define BS 32

// anchors [level][anchor][xy]
__constant__ float c_anch[3][3][2] = {
    {{116.f, 90.f}, {156.f, 198.f}, {373.f, 326.f}},
    {{ 30.f, 61.f}, { 62.f,  45.f}, { 59.f, 119.f}},
    {{ 10.f, 13.f}, { 16.f,  30.f}, { 33.f,  23.f}}
};
__constant__ float c_stride[3] = {32.f, 16.f, 8.f};
__constant__ int   c_H[3]      = {13, 26, 52};

__device__ __forceinline__ float softplusf(float z) {
    // log(1+exp(z)), stable
    return fmaxf(z, 0.f) + log1pf(expf(-fabsf(z)));
}
__device__ __forceinline__ float sigmoidf(float z) {
    return 1.f / (1.f + expf(-z));
}

// Block mapping: blockIdx.x in [0,42): [0,2)->lvl0, [2,10)->lvl1, [10,42)->lvl2
// blockIdx.y = batch index. 256 threads, 1 cell per thread.
__global__ __launch_bounds__(256)
void yolo_loss_kernel(const float* __restrict__ x0,
                      const float* __restrict__ x1,
                      const float* __restrict__ x2,
                      const float* __restrict__ gtb,   // [BS,T,4] xyxy pixels, -1 pad
                      const int*   __restrict__ gtl,   // [BS,T]
                      float* __restrict__ out)
{
    const int bx  = blockIdx.x;
    const int b   = blockIdx.y;
    const int tid = threadIdx.x;

    int lvl, nblk;
    if (bx < 2)       { lvl = 0; nblk = bx; }
    else if (bx < 10) { lvl = 1; nblk = bx - 2; }
    else              { lvl = 2; nblk = bx - 10; }

    const float* x = (lvl == 0) ? x0 : (lvl == 1) ? x1 : x2;
    const int   H  = c_H[lvl];
    const int   W  = H;
    const int   HW = H * W;
    const int   N  = 3 * HW;
    const float stride = c_stride[lvl];
    const float inv_s  = 1.f / stride;

    float sax[3], say[3];
#pragma unroll
    for (int a = 0; a < 3; a++) {
        sax[a] = c_anch[lvl][a][0] * inv_s;
        say[a] = c_anch[lvl][a][1] * inv_s;
    }

    // ---- per-target precompute in shared memory ----
    __shared__ float s_bx1[T], s_by1[T], s_bx2[T], s_by2[T], s_area[T];
    __shared__ float s_tx[T], s_ty[T], s_tw[T], s_th[T];
    __shared__ int   s_flat[T], s_valid[T], s_label[T];

    if (tid < T) {
        const float* g = gtb + ((size_t)b * T + tid) * 4;
        float a1 = g[0], b1 = g[1], a2 = g[2], b2 = g[3];
        int valid = (a1 != -1.f) || (b1 != -1.f) || (a2 != -1.f) || (b2 != -1.f);
        s_valid[tid] = valid;

        float tbx1 = a1 * inv_s, tby1 = b1 * inv_s;
        float tbx2 = a2 * inv_s, tby2 = b2 * inv_s;
        s_bx1[tid] = tbx1; s_by1[tid] = tby1;
        s_bx2[tid] = tbx2; s_by2[tid] = tby2;
        s_area[tid] = (tbx2 - tbx1) * (tby2 - tby1);

        float gw  = (a2 - a1) * inv_s;
        float gh  = (b2 - b1) * inv_s;
        float gxc = (a1 + a2) * (0.5f * inv_s);
        float gyc = (b1 + b2) * (0.5f * inv_s);
        int gi = min(max((int)gxc, 0), W - 1);
        int gj = min(max((int)gyc, 0), H - 1);

        // best anchor by shape IoU (first max wins -> strict >)
        int best = 0; float bi = -1.f;
#pragma unroll
        for (int a = 0; a < 3; a++) {
            float inter = fminf(gw, sax[a]) * fminf(gh, say[a]);
            float u = gw * gh + sax[a] * say[a] - inter + 1e-16f;
            float io = inter / u;
            if (io > bi) { bi = io; best = a; }
        }
        s_flat[tid] = best * HW + gj * W + gi;
        s_tx[tid]   = gxc - (float)gi;
        s_ty[tid]   = gyc - (float)gj;
        s_tw[tid]   = logf(gw / sax[best] + 1e-16f);
        s_th[tid]   = logf(gh / say[best] + 1e-16f);
        s_label[tid] = min(max(gtl[b * T + tid], 0), NC - 1);
    }
    __syncthreads();

    // ---- per-cell loss ----
    float loss = 0.f;
    int n = nblk * 256 + tid;
    if (n < N) {
        int a   = n / HW;
        int rem = n - a * HW;
        int j   = rem / W;
        int i   = rem - j * W;

        const float* xp = x + (size_t)b * 255 * HW + (size_t)a * 85 * HW + rem;
        float zx = xp[0];
        float zy = xp[HW];
        float zw = xp[2 * HW];
        float zh = xp[3 * HW];
        float zc = xp[4 * HW];

        float px = sigmoidf(zx);
        float py = sigmoidf(zy);
        float bxc = px + (float)i;
        float byc = py + (float)j;
        float bw = expf(zw) * sax[a];
        float bh = expf(zh) * say[a];
        float pbx1 = bxc - bw * 0.5f, pby1 = byc - bh * 0.5f;
        float pbx2 = bxc + bw * 0.5f, pby2 = byc + bh * 0.5f;
        float areap = (pbx2 - pbx1) * (pby2 - pby1);

        int Lig = -1, Lpos = -1;
#pragma unroll
        for (int t = 0; t < T; t++) {
            if (!s_valid[t]) continue;
            float ix1 = fmaxf(pbx1, s_bx1[t]);
            float iy1 = fmaxf(pby1, s_by1[t]);
            float ix2 = fminf(pbx2, s_bx2[t]);
            float iy2 = fminf(pby2, s_by2[t]);
            float inter = fmaxf(ix2 - ix1, 0.f) * fmaxf(iy2 - iy1, 0.f);
            float iou = inter / (areap + s_area[t] - inter + 1e-16f);
            if (iou > 0.5f)     Lig = t;      // ascending loop == last writer wins
            if (s_flat[t] == n) Lpos = t;
        }

        bool pos = (Lpos >= 0) && (Lpos >= Lig);
        if (pos) {
            int w = Lpos;
            float tx = s_tx[w], ty = s_ty[w];
            // BCE(sigmoid(z), t) = t*softplus(-z) + (1-t)*softplus(z)
            float bxl = tx * softplusf(-zx) + (1.f - tx) * softplusf(zx);
            float byl = ty * softplusf(-zy) + (1.f - ty) * softplusf(zy);
            loss += 2.5f * (bxl + byl);
            float dw = zw - s_tw[w];
            float dh = zh - s_th[w];
            loss += 2.5f * (dw * dw + dh * dh);
            loss += softplusf(-zc);  // conf, target 1

            // class target bitmask: ANY valid target mapping to this cell sets its label bit
            unsigned m0 = 0, m1 = 0, m2 = 0;
#pragma unroll
            for (int t = 0; t < T; t++) {
                if (s_valid[t] && s_flat[t] == n) {
                    int l = s_label[t];
                    if (l < 32)      m0 |= 1u << l;
                    else if (l < 64) m1 |= 1u << (l - 32);
                    else             m2 |= 1u << (l - 64);
                }
            }
            const float* cp = xp + 5 * HW;
#pragma unroll 8
            for (int c = 0; c < NC; c++) {
                float z = cp[(size_t)c * HW];
                unsigned bit = ((c < 32 ? (m0 >> c)
                               : c < 64 ? (m1 >> (c - 32))
                                        : (m2 >> (c - 64))) & 1u);
                loss += bit ? softplusf(-z) : softplusf(z);
            }
        } else if (Lig < 0) {
            // negative cell: conf target 0
            loss += softplusf(zc);
        }
        // else maskf == -1: excluded entirely
    }

    // ---- block reduction ----
    __shared__ float s_red[256];
    s_red[tid] = loss;
    __syncthreads();
#pragma unroll
    for (int s = 128; s > 0; s >>= 1) {
        if (tid < s) s_red[tid] += s_red[tid + s];
        __syncthreads();
    }
    if (tid == 0) atomicAdd(out, s_red[0] * (1.f / (float)BS));
}

extern "C" void kernel_launch(void* const* d_in, const int* in_sizes, int n_in,
                              void* d_out, int out_size)
{
    const float* x0  = (const float*)d_in[0];
    const float* x1  = (const float*)d_in[1];
    const float* x2  = (const float*)d_in[2];
    const float* gtb = (const float*)d_in[3];
    const int*   gtl = (const int*)  d_in[4];
    float* out = (float*)d_out;

    cudaMemsetAsync(out, 0, sizeof(float));

    // blocks: lvl0 ceil(507/256)=2, lvl1 ceil(2028/256)=8, lvl2 ceil(8112/256)=32
    dim3 grid(42, BS);
    yolo_loss_kernel<<<grid, 256>>>(x0, x1, x2, gtb, gtl, out);
}

// round 2
// speedup vs baseline: 2.8772x; 2.8772x over previous
#include <cuda_runtime.h>
#include <math.h>

#define T 20
#define NC 80
#define BS 32

__constant__ float c_anch[3][3][2] = {
    {{116.f, 90.f}, {156.f, 198.f}, {373.f, 326.f}},
    {{ 30.f, 61.f}, { 62.f,  45.f}, { 59.f, 119.f}},
    {{ 10.f, 13.f}, { 16.f,  30.f}, { 33.f,  23.f}}
};
__constant__ float c_stride[3] = {32.f, 16.f, 8.f};
__constant__ int   c_H[3]      = {13, 26, 52};

// stable softplus with fast intrinsics: log(1+exp(z))
__device__ __forceinline__ float sp(float z) {
    return fmaxf(z, 0.f) + __logf(1.f + __expf(-fabsf(z)));
}

// Block mapping: blockIdx.x in [0,42): [0,2)->lvl0, [2,10)->lvl1, [10,42)->lvl2
// blockIdx.y = batch. 256 threads, 1 cell/thread.
__global__ __launch_bounds__(256)
void yolo_loss_kernel(const float* __restrict__ x0,
                      const float* __restrict__ x1,
                      const float* __restrict__ x2,
                      const float* __restrict__ gtb,
                      const int*   __restrict__ gtl,
                      float* __restrict__ out)
{
    const int bx   = blockIdx.x;
    const int b    = blockIdx.y;
    const int tid  = threadIdx.x;
    const int lane = tid & 31;
    const int wrp  = tid >> 5;

    int lvl, nblk;
    if (bx < 2)       { lvl = 0; nblk = bx; }
    else if (bx < 10) { lvl = 1; nblk = bx - 2; }
    else              { lvl = 2; nblk = bx - 10; }

    const float* x = (lvl == 0) ? x0 : (lvl == 1) ? x1 : x2;
    const int   H  = c_H[lvl];
    const int   W  = H;
    const int   HW = H * W;
    const int   N  = 3 * HW;
    const float inv_s = 1.f / c_stride[lvl];

    float sax[3], say[3];
#pragma unroll
    for (int a = 0; a < 3; a++) {
        sax[a] = c_anch[lvl][a][0] * inv_s;
        say[a] = c_anch[lvl][a][1] * inv_s;
    }

    // ---- per-target precompute ----
    __shared__ float4 s_box[T];    // x1,y1,x2,y2 (grid units); degenerate if invalid
    __shared__ float4 s_tgt[T];    // tx,ty,tw,th
    __shared__ float  s_area[T];
    __shared__ int    s_flat[T];   // -1 if invalid
    __shared__ int    s_lab[T];
    __shared__ float  s_wred[8];

    if (tid < T) {
        const float* g = gtb + ((size_t)b * T + tid) * 4;
        float a1 = g[0], b1 = g[1], a2 = g[2], b2 = g[3];
        bool valid = (a1 != -1.f) || (b1 != -1.f) || (a2 != -1.f) || (b2 != -1.f);

        float tbx1 = a1 * inv_s, tby1 = b1 * inv_s;
        float tbx2 = a2 * inv_s, tby2 = b2 * inv_s;
        if (!valid) { tbx1 = tby1 = tbx2 = tby2 = 0.f; }
        s_box[tid]  = make_float4(tbx1, tby1, tbx2, tby2);
        s_area[tid] = (tbx2 - tbx1) * (tby2 - tby1);

        float gw  = (a2 - a1) * inv_s;
        float gh  = (b2 - b1) * inv_s;
        float gxc = (a1 + a2) * (0.5f * inv_s);
        float gyc = (b1 + b2) * (0.5f * inv_s);
        int gi = min(max((int)gxc, 0), W - 1);
        int gj = min(max((int)gyc, 0), H - 1);

        int best = 0; float bi = -1.f;
#pragma unroll
        for (int a = 0; a < 3; a++) {
            float inter = fminf(gw, sax[a]) * fminf(gh, say[a]);
            float u = gw * gh + sax[a] * say[a] - inter + 1e-16f;
            float io = inter / u;
            if (io > bi) { bi = io; best = a; }
        }
        s_flat[tid] = valid ? (best * HW + gj * W + gi) : -1;
        s_tgt[tid]  = make_float4(gxc - (float)gi, gyc - (float)gj,
                                  logf(gw / sax[best] + 1e-16f),
                                  logf(gh / say[best] + 1e-16f));
        s_lab[tid]  = min(max(gtl[b * T + tid], 0), NC - 1);
    }
    __syncthreads();

    const int n = nblk * 256 + tid;
    const bool active = (n < N);

    float loss = 0.f;
    bool pos = false;
    unsigned m0 = 0, m1 = 0, m2 = 0;
    float zx = 0.f, zy = 0.f, zw = 0.f, zh = 0.f, zc = 0.f;
    int Lpos = -1;
    const size_t base_b = (size_t)b * 255 * HW;

    if (active) {
        int a   = n / HW;
        int rem = n - a * HW;
        int j   = rem / W;
        int i   = rem - j * W;

        const float* xp = x + base_b + (size_t)a * 85 * HW + rem;
        zx = xp[0];
        zy = xp[(size_t)HW];
        zw = xp[(size_t)2 * HW];
        zh = xp[(size_t)3 * HW];
        zc = xp[(size_t)4 * HW];

        // decode (approx ok: only feeds ignore threshold)
        float px = __fdividef(1.f, 1.f + __expf(-zx));
        float py = __fdividef(1.f, 1.f + __expf(-zy));
        float bxc = px + (float)i;
        float byc = py + (float)j;
        float bw = __expf(zw) * sax[a];
        float bh = __expf(zh) * say[a];
        float pbx1 = bxc - bw * 0.5f, pby1 = byc - bh * 0.5f;
        float pbx2 = bxc + bw * 0.5f, pby2 = byc + bh * 0.5f;
        float areap = bw * bh;

        int Lig = -1;
#pragma unroll
        for (int t = 0; t < T; t++) {
            float4 bb = s_box[t];
            float iw = fminf(pbx2, bb.z) - fmaxf(pbx1, bb.x);
            float ih = fminf(pby2, bb.w) - fmaxf(pby1, bb.y);
            float inter = fmaxf(iw, 0.f) * fmaxf(ih, 0.f);
            // iou > 0.5  <=>  3*inter > areap + areat + eps
            if (3.f * inter > areap + s_area[t] + 1e-16f) Lig = t;
            if (s_flat[t] == n) {
                Lpos = t;
                int l = s_lab[t];
                if (l < 32)      m0 |= 1u << l;
                else if (l < 64) m1 |= 1u << (l - 32);
                else             m2 |= 1u << (l - 64);
            }
        }

        pos = (Lpos >= 0) && (Lpos >= Lig);
        if (pos) {
            float4 tg = s_tgt[Lpos];
            float bxl = tg.x * sp(-zx) + (1.f - tg.x) * sp(zx);
            float byl = tg.y * sp(-zy) + (1.f - tg.y) * sp(zy);
            float dw = zw - tg.z;
            float dh = zh - tg.w;
            loss = 2.5f * (bxl + byl + dw * dw + dh * dh) + sp(-zc);
        } else if (Lig < 0) {
            loss = sp(zc);
        }
    }

    // ---- warp-cooperative class loss for rare positive cells ----
    // BCE(sigmoid(z),1) = softplus(z) - z ; BCE(sigmoid(z),0) = softplus(z)
    unsigned ballot = __ballot_sync(0xffffffffu, pos);
    while (ballot) {
        int src = __ffs(ballot) - 1;
        ballot &= ballot - 1;
        int ns       = __shfl_sync(0xffffffffu, n,  src);
        unsigned M0  = __shfl_sync(0xffffffffu, m0, src);
        unsigned M1  = __shfl_sync(0xffffffffu, m1, src);
        unsigned M2  = __shfl_sync(0xffffffffu, m2, src);
        int as   = ns / HW;
        int rems = ns - as * HW;
        const float* cps = x + base_b + (size_t)as * 85 * HW + rems + (size_t)5 * HW;

        float acc = 0.f;
        {   // c = lane (0..31)
            float z = __ldg(cps + (size_t)lane * HW);
            acc += sp(z) - (((M0 >> lane) & 1u) ? z : 0.f);
        }
        {   // c = lane+32
            float z = __ldg(cps + (size_t)(lane + 32) * HW);
            acc += sp(z) - (((M1 >> lane) & 1u) ? z : 0.f);
        }
        if (lane < 16) {  // c = lane+64 (64..79)
            float z = __ldg(cps + (size_t)(lane + 64) * HW);
            acc += sp(z) - (((M2 >> lane) & 1u) ? z : 0.f);
        }
        loss += acc;  // partials flow into block reduction
    }

    // ---- reduction: warp shfl -> shared -> warp0 -> atomic ----
#pragma unroll
    for (int o = 16; o > 0; o >>= 1)
        loss += __shfl_down_sync(0xffffffffu, loss, o);
    if (lane == 0) s_wred[wrp] = loss;
    __syncthreads();
    if (wrp == 0) {
        float v = (lane < 8) ? s_wred[lane] : 0.f;
#pragma unroll
        for (int o = 4; o > 0; o >>= 1)
            v += __shfl_down_sync(0xffffffffu, v, o);
        if (lane == 0) atomicAdd(out, v * (1.f / (float)BS));
    }
}

extern "C" void kernel_launch(void* const* d_in, const int* in_sizes, int n_in,
                              void* d_out, int out_size)
{
    const float* x0  = (const float*)d_in[0];
    const float* x1  = (const float*)d_in[1];
    const float* x2  = (const float*)d_in[2];
    const float* gtb = (const float*)d_in[3];
    const int*   gtl = (const int*)  d_in[4];
    float* out = (float*)d_out;

    cudaMemsetAsync(out, 0, sizeof(float));
    dim3 grid(42, BS);
    yolo_loss_kernel<<<grid, 256>>>(x0, x1, x2, gtb, gtl, out);
}

// round 3
// speedup vs baseline: 3.0181x; 1.0490x over previous
#include <cuda_runtime.h>
#include <math.h>

#define T 20
#define NC 80
#define BS 32

__constant__ float c_anch[3][3][2] = {
    {{116.f, 90.f}, {156.f, 198.f}, {373.f, 326.f}},
    {{ 30.f, 61.f}, { 62.f,  45.f}, { 59.f, 119.f}},
    {{ 10.f, 13.f}, { 16.f,  30.f}, { 33.f,  23.f}}
};
__constant__ float c_stride[3] = {32.f, 16.f, 8.f};
__constant__ int   c_H[3]      = {13, 26, 52};

// stable softplus, fast intrinsics
__device__ __forceinline__ float sp(float z) {
    return fmaxf(z, 0.f) + __logf(1.f + __expf(-fabsf(z)));
}

// grid: (21, 32). bx==0 -> lvl0; bx in [1,5) -> lvl1; bx in [5,21) -> lvl2.
// 256 threads, 2 cells per thread (512 cells per block) -> single wave.
__global__ __launch_bounds__(256)
void yolo_loss_kernel(const float* __restrict__ x0,
                      const float* __restrict__ x1,
                      const float* __restrict__ x2,
                      const float* __restrict__ gtb,
                      const int*   __restrict__ gtl,
                      float* __restrict__ out)
{
    const int bx   = blockIdx.x;
    const int b    = blockIdx.y;
    const int tid  = threadIdx.x;
    const int lane = tid & 31;
    const int wrp  = tid >> 5;

    int lvl, nblk;
    if (bx == 0)     { lvl = 0; nblk = 0; }
    else if (bx < 5) { lvl = 1; nblk = bx - 1; }
    else             { lvl = 2; nblk = bx - 5; }

    const float* x = (lvl == 0) ? x0 : (lvl == 1) ? x1 : x2;
    const int   H  = c_H[lvl];
    const int   W  = H;
    const int   HW = H * W;
    const int   N  = 3 * HW;
    const float inv_s = 1.f / c_stride[lvl];

    float sax[3], say[3];
#pragma unroll
    for (int a = 0; a < 3; a++) {
        sax[a] = c_anch[lvl][a][0] * inv_s;
        say[a] = c_anch[lvl][a][1] * inv_s;
    }

    // ---- shared target tables + positive-cell scatter table ----
    __shared__ float4 s_box[T];    // x1,y1,x2,y2 grid units (degenerate if invalid)
    __shared__ float  s_aeps[T];   // area + 1e-16
    __shared__ float4 s_tgt[T];    // tx,ty,tw,th
    __shared__ int    s_flat[T];   // -1 if invalid
    __shared__ int    s_lab[T];
    __shared__ int    s_pos[512];  // winning target per block-local cell, -1 none
    __shared__ float  s_wred[8];

    const int base = nblk * 512;

    // phase A: init s_pos, compute per-target data
    s_pos[tid]       = -1;
    s_pos[tid + 256] = -1;
    if (tid < T) {
        const float* g = gtb + ((size_t)b * T + tid) * 4;
        float a1 = g[0], b1 = g[1], a2 = g[2], b2 = g[3];
        bool valid = (a1 != -1.f) || (b1 != -1.f) || (a2 != -1.f) || (b2 != -1.f);

        float tbx1 = a1 * inv_s, tby1 = b1 * inv_s;
        float tbx2 = a2 * inv_s, tby2 = b2 * inv_s;
        if (!valid) { tbx1 = tby1 = tbx2 = tby2 = 0.f; }
        s_box[tid]  = make_float4(tbx1, tby1, tbx2, tby2);
        s_aeps[tid] = (tbx2 - tbx1) * (tby2 - tby1) + 1e-16f;

        float gw  = (a2 - a1) * inv_s;
        float gh  = (b2 - b1) * inv_s;
        float gxc = (a1 + a2) * (0.5f * inv_s);
        float gyc = (b1 + b2) * (0.5f * inv_s);
        int gi = min(max((int)gxc, 0), W - 1);
        int gj = min(max((int)gyc, 0), H - 1);

        int best = 0; float bi = -1.f;
#pragma unroll
        for (int a = 0; a < 3; a++) {
            float inter = fminf(gw, sax[a]) * fminf(gh, say[a]);
            float u = gw * gh + sax[a] * say[a] - inter + 1e-16f;
            float io = inter / u;
            if (io > bi) { bi = io; best = a; }
        }
        s_flat[tid] = valid ? (best * HW + gj * W + gi) : -1;
        s_tgt[tid]  = make_float4(gxc - (float)gi, gyc - (float)gj,
                                  logf(gw / sax[best] + 1e-16f),
                                  logf(gh / say[best] + 1e-16f));
        s_lab[tid]  = min(max(gtl[b * T + tid], 0), NC - 1);
    }
    __syncthreads();

    // phase B: scatter winners (last writer wins == max t)
    if (tid < T) {
        int f = s_flat[tid];
        int loc = f - base;
        if (f >= 0 && loc >= 0 && loc < 512) atomicMax(&s_pos[loc], tid);
    }
    __syncthreads();

    const size_t base_b = (size_t)b * 255 * HW;

    const int n0 = base + tid;
    const int n1 = base + 256 + tid;
    const bool act0 = (n0 < N);
    const bool act1 = (n1 < N);

    // ---- load + decode both cells ----
    float zx0=0,zy0=0,zw0=0,zh0=0,zc0=0, zx1=0,zy1=0,zw1=0,zh1=0,zc1=0;
    float px1_0=0,py1_0=0,px2_0=0,py2_0=0,ap0=0;
    float px1_1=0,py1_1=0,px2_1=0,py2_1=0,ap1=0;
    int a0=0, a1i=0, rem0=0, rem1=0;

    if (act0) {
        a0   = n0 / HW; rem0 = n0 - a0 * HW;
        int j = rem0 / W, i = rem0 - (rem0 / W) * W;
        const float* xp = x + base_b + (size_t)a0 * 85 * HW + rem0;
        zx0 = xp[0]; zy0 = xp[(size_t)HW]; zw0 = xp[(size_t)2*HW];
        zh0 = xp[(size_t)3*HW]; zc0 = xp[(size_t)4*HW];
        float sx = __fdividef(1.f, 1.f + __expf(-zx0));
        float sy = __fdividef(1.f, 1.f + __expf(-zy0));
        float bxc = sx + (float)i, byc = sy + (float)j;
        float bw = __expf(zw0) * sax[a0], bh = __expf(zh0) * say[a0];
        px1_0 = bxc - bw*0.5f; py1_0 = byc - bh*0.5f;
        px2_0 = bxc + bw*0.5f; py2_0 = byc + bh*0.5f;
        ap0 = bw * bh;
    }
    if (act1) {
        a1i  = n1 / HW; rem1 = n1 - a1i * HW;
        int j = rem1 / W, i = rem1 - (rem1 / W) * W;
        const float* xp = x + base_b + (size_t)a1i * 85 * HW + rem1;
        zx1 = xp[0]; zy1 = xp[(size_t)HW]; zw1 = xp[(size_t)2*HW];
        zh1 = xp[(size_t)3*HW]; zc1 = xp[(size_t)4*HW];
        float sx = __fdividef(1.f, 1.f + __expf(-zx1));
        float sy = __fdividef(1.f, 1.f + __expf(-zy1));
        float bxc = sx + (float)i, byc = sy + (float)j;
        float bw = __expf(zw1) * sax[a1i], bh = __expf(zh1) * say[a1i];
        px1_1 = bxc - bw*0.5f; py1_1 = byc - bh*0.5f;
        px2_1 = bxc + bw*0.5f; py2_1 = byc + bh*0.5f;
        ap1 = bw * bh;
    }

    // ---- shared ignore loop, 2 independent chains ----
    int Lig0 = -1, Lig1 = -1;
#pragma unroll
    for (int t = 0; t < T; t++) {
        float4 bb = s_box[t];
        float rhs = s_aeps[t];
        float iw0 = fminf(px2_0, bb.z) - fmaxf(px1_0, bb.x);
        float ih0 = fminf(py2_0, bb.w) - fmaxf(py1_0, bb.y);
        float in0 = fmaxf(iw0, 0.f) * fmaxf(ih0, 0.f);
        if (3.f * in0 > ap0 + rhs) Lig0 = t;
        float iw1 = fminf(px2_1, bb.z) - fmaxf(px1_1, bb.x);
        float ih1 = fminf(py2_1, bb.w) - fmaxf(py1_1, bb.y);
        float in1 = fmaxf(iw1, 0.f) * fmaxf(ih1, 0.f);
        if (3.f * in1 > ap1 + rhs) Lig1 = t;
    }

    const int Lp0 = act0 ? s_pos[tid]       : -1;
    const int Lp1 = act1 ? s_pos[tid + 256] : -1;
    const bool pos0 = (Lp0 >= 0) && (Lp0 >= Lig0);
    const bool pos1 = (Lp1 >= 0) && (Lp1 >= Lig1);

    float loss = 0.f;
    unsigned m0a=0, m1a=0, m2a=0, m0b=0, m1b=0, m2b=0;

    if (pos0) {
        float4 tg = s_tgt[Lp0];
        float bxl = tg.x * sp(-zx0) + (1.f - tg.x) * sp(zx0);
        float byl = tg.y * sp(-zy0) + (1.f - tg.y) * sp(zy0);
        float dw = zw0 - tg.z, dh = zh0 - tg.w;
        loss += 2.5f * (bxl + byl + dw*dw + dh*dh) + sp(-zc0);
#pragma unroll
        for (int t = 0; t < T; t++)
            if (s_flat[t] == n0) {
                int l = s_lab[t];
                if (l < 32) m0a |= 1u << l; else if (l < 64) m1a |= 1u << (l-32); else m2a |= 1u << (l-64);
            }
    } else if (act0 && Lig0 < 0) {
        loss += sp(zc0);
    }
    if (pos1) {
        float4 tg = s_tgt[Lp1];
        float bxl = tg.x * sp(-zx1) + (1.f - tg.x) * sp(zx1);
        float byl = tg.y * sp(-zy1) + (1.f - tg.y) * sp(zy1);
        float dw = zw1 - tg.z, dh = zh1 - tg.w;
        loss += 2.5f * (bxl + byl + dw*dw + dh*dh) + sp(-zc1);
#pragma unroll
        for (int t = 0; t < T; t++)
            if (s_flat[t] == n1) {
                int l = s_lab[t];
                if (l < 32) m0b |= 1u << l; else if (l < 64) m1b |= 1u << (l-32); else m2b |= 1u << (l-64);
            }
    } else if (act1 && Lig1 < 0) {
        loss += sp(zc1);
    }

    // ---- warp-cooperative class loss (rare positives) ----
    // BCE(sig(z),1) = softplus(z) - z ; BCE(sig(z),0) = softplus(z)
#pragma unroll
    for (int c = 0; c < 2; c++) {
        bool p       = c ? pos1 : pos0;
        int  nn      = c ? n1   : n0;
        unsigned M0t = c ? m0b : m0a, M1t = c ? m1b : m1a, M2t = c ? m2b : m2a;
        unsigned ballot = __ballot_sync(0xffffffffu, p);
        while (ballot) {
            int src = __ffs(ballot) - 1;
            ballot &= ballot - 1;
            int ns      = __shfl_sync(0xffffffffu, nn,  src);
            unsigned M0 = __shfl_sync(0xffffffffu, M0t, src);
            unsigned M1 = __shfl_sync(0xffffffffu, M1t, src);
            unsigned M2 = __shfl_sync(0xffffffffu, M2t, src);
            int as   = ns / HW;
            int rems = ns - as * HW;
            const float* cps = x + base_b + (size_t)as * 85 * HW + rems + (size_t)5 * HW;
            float acc;
            {   float z = __ldg(cps + (size_t)lane * HW);
                acc = sp(z) - (((M0 >> lane) & 1u) ? z : 0.f); }
            {   float z = __ldg(cps + (size_t)(lane + 32) * HW);
                acc += sp(z) - (((M1 >> lane) & 1u) ? z : 0.f); }
            if (lane < 16) {
                float z = __ldg(cps + (size_t)(lane + 64) * HW);
                acc += sp(z) - (((M2 >> lane) & 1u) ? z : 0.f); }
            loss += acc;
        }
    }

    // ---- reduction ----
#pragma unroll
    for (int o = 16; o > 0; o >>= 1)
        loss += __shfl_down_sync(0xffffffffu, loss, o);
    if (lane == 0) s_wred[wrp] = loss;
    __syncthreads();
    if (wrp == 0) {
        float v = (lane < 8) ? s_wred[lane] : 0.f;
#pragma unroll
        for (int o = 4; o > 0; o >>= 1)
            v += __shfl_down_sync(0xffffffffu, v, o);
        if (lane == 0) atomicAdd(out, v * (1.f / (float)BS));
    }
}

extern "C" void kernel_launch(void* const* d_in, const int* in_sizes, int n_in,
                              void* d_out, int out_size)
{
    const float* x0  = (const float*)d_in[0];
    const float* x1  = (const float*)d_in[1];
    const float* x2  = (const float*)d_in[2];
    const float* gtb = (const float*)d_in[3];
    const int*   gtl = (const int*)  d_in[4];
    float* out = (float*)d_out;

    cudaMemsetAsync(out, 0, sizeof(float));
    dim3 grid(21, BS);
    yolo_loss_kernel<<<grid, 256>>>(x0, x1, x2, gtb, gtl, out);
}